// round 1
// baseline (speedup 1.0000x reference)
#include <cuda_runtime.h>
#include <math.h>

#define T_ 70
#define B_ 64
#define NTOK 33278
#define NINP_ 400
#define NHID_ 1150

// ---------------- scratch (static device globals; no runtime alloc) ----------
__device__ float g_x0   [T_*B_*NINP_];        // embedded input       (4480 x 400)
__device__ float g_xpre0[T_*B_*4*NHID_];      // layer0 input proj    (4480 x 4600)
__device__ float g_hs0  [T_*B_*NHID_];        // layer0 outputs
__device__ float g_xpre1[T_*B_*4*NHID_];      // layer1 input proj
__device__ float g_hs1  [T_*B_*NHID_];        // layer1 outputs
__device__ float g_xpre2[T_*B_*4*NINP_];      // layer2 input proj    (4480 x 1600)
__device__ float g_hs2  [T_*B_*NINP_];        // layer2 outputs
__device__ float g_h    [B_*NHID_];           // current h (max D)
__device__ float g_c    [B_*NHID_];           // current c
__device__ float g_gates[B_*4*NHID_];         // activated gates for one step

// ---------------- embedding gather ------------------------------------------
__global__ void embed_k(const int* __restrict__ inp, const float* __restrict__ emb_w) {
    int token = blockIdx.x;                  // 0..4479  (= t*B + b)
    int tok   = inp[token];
    const float* src = emb_w + (size_t)tok * NINP_;
    float* dst = g_x0 + (size_t)token * NINP_;
    for (int j = threadIdx.x; j < NINP_; j += blockDim.x) dst[j] = src[j];
}

// ---------------- h/c init ---------------------------------------------------
__global__ void init_hc(const float* __restrict__ h0, const float* __restrict__ c0, int n) {
    int i = blockIdx.x * blockDim.x + threadIdx.x;
    if (i < n) { g_h[i] = h0[i]; g_c[i] = c0[i]; }
}

// ---------------- generic NT SGEMM:  C[M,N] = A[M,K] * B[N,K]^T + bias[N] ----
// 128x128 tile, BK=16, 256 threads, 8x8 microtile, interleaved col/row mapping
__global__ __launch_bounds__(256) void sgemm_nt(
    const float* __restrict__ A, const float* __restrict__ Bm,
    const float* __restrict__ bias, float* __restrict__ C,
    int M, int N, int K)
{
    __shared__ float As[128][17];
    __shared__ float Bs[128][17];
    int tid = threadIdx.x;
    int tx = tid & 15, ty = tid >> 4;
    int m0 = blockIdx.y * 128, n0 = blockIdx.x * 128;

    float acc[8][8];
    #pragma unroll
    for (int i = 0; i < 8; ++i)
        #pragma unroll
        for (int j = 0; j < 8; ++j) acc[i][j] = 0.f;

    for (int k0 = 0; k0 < K; k0 += 16) {
        #pragma unroll
        for (int it = 0; it < 8; ++it) {
            int idx = tid + it * 256;
            int r = idx >> 4, c = idx & 15;
            int gk = k0 + c;
            int gm = m0 + r;
            As[r][c] = (gm < M && gk < K) ? A[(size_t)gm * K + gk] : 0.f;
            int gn = n0 + r;
            Bs[r][c] = (gn < N && gk < K) ? Bm[(size_t)gn * K + gk] : 0.f;
        }
        __syncthreads();
        #pragma unroll
        for (int c = 0; c < 16; ++c) {
            float a[8], b[8];
            #pragma unroll
            for (int i = 0; i < 8; ++i) a[i] = As[ty + 16 * i][c];
            #pragma unroll
            for (int j = 0; j < 8; ++j) b[j] = Bs[tx + 16 * j][c];
            #pragma unroll
            for (int i = 0; i < 8; ++i)
                #pragma unroll
                for (int j = 0; j < 8; ++j) acc[i][j] += a[i] * b[j];
        }
        __syncthreads();
    }

    #pragma unroll
    for (int i = 0; i < 8; ++i) {
        int m = m0 + ty + 16 * i;
        if (m >= M) continue;
        #pragma unroll
        for (int j = 0; j < 8; ++j) {
            int n = n0 + tx + 16 * j;
            if (n < N) C[(size_t)m * N + n] = acc[i][j] + bias[n];
        }
    }
}

// ---------------- recurrent step GEMM + gate activation ----------------------
// gates[b][n] = act( xpre[t,b,n] + sum_k h[b,k]*wh[n,k] + bh[n] )
// tile: 64 (batch) x 32 (gate cols); 256 threads; each thread: 4 rows x 2 cols
__global__ __launch_bounds__(256) void lstm_step_gemm(
    const float* __restrict__ wh, const float* __restrict__ bh,
    const float* __restrict__ xpre, int t, int N, int K)
{
    __shared__ float Hs[64][17];
    __shared__ float Ws[32][17];
    int tid = threadIdx.x;
    int tx = tid & 15, ty = tid >> 4;   // tx: col pair base, ty: row base (0..15)
    int n0 = blockIdx.x * 32;

    float acc[4][2];
    #pragma unroll
    for (int r = 0; r < 4; ++r) { acc[r][0] = 0.f; acc[r][1] = 0.f; }

    for (int k0 = 0; k0 < K; k0 += 16) {
        #pragma unroll
        for (int it = 0; it < 4; ++it) {         // 64*16 = 1024 elems
            int idx = tid + it * 256;
            int r = idx >> 4, c = idx & 15;
            int gk = k0 + c;
            Hs[r][c] = (gk < K) ? g_h[r * K + gk] : 0.f;
        }
        #pragma unroll
        for (int it = 0; it < 2; ++it) {         // 32*16 = 512 elems
            int idx = tid + it * 256;
            int r = idx >> 4, c = idx & 15;
            int gn = n0 + r, gk = k0 + c;
            Ws[r][c] = (gn < N && gk < K) ? wh[(size_t)gn * K + gk] : 0.f;
        }
        __syncthreads();
        #pragma unroll
        for (int c = 0; c < 16; ++c) {
            float w0 = Ws[tx][c];
            float w1 = Ws[tx + 16][c];
            #pragma unroll
            for (int r = 0; r < 4; ++r) {
                float hv = Hs[ty + 16 * r][c];
                acc[r][0] += hv * w0;
                acc[r][1] += hv * w1;
            }
        }
        __syncthreads();
    }

    int D3 = 3 * (N >> 2);
    const float* xp = xpre + (size_t)t * B_ * N;
    #pragma unroll
    for (int jj = 0; jj < 2; ++jj) {
        int n = n0 + tx + 16 * jj;
        if (n >= N) continue;
        float bn = bh[n];
        #pragma unroll
        for (int r = 0; r < 4; ++r) {
            int b = ty + 16 * r;
            float pre = acc[r][jj] + xp[(size_t)b * N + n] + bn;
            float v = (n < D3) ? (1.f / (1.f + expf(-pre))) : tanhf(pre);
            g_gates[(size_t)b * N + n] = v;
        }
    }
}

// ---------------- pointwise cell update --------------------------------------
__global__ void lstm_point(float* __restrict__ hs, int t, int D) {
    int i = blockIdx.x * blockDim.x + threadIdx.x;
    if (i >= B_ * D) return;
    int b = i / D, j = i - b * D;
    int N = 4 * D;
    float f  = g_gates[(size_t)b * N + j];
    float ig = g_gates[(size_t)b * N + D + j];
    float o  = g_gates[(size_t)b * N + 2 * D + j];
    float g  = g_gates[(size_t)b * N + 3 * D + j];
    float c  = f * g_c[i] + ig * g;
    g_c[i] = c;
    float h = o * tanhf(c);
    g_h[i] = h;
    hs[(size_t)t * B_ * D + i] = h;
}

// ---------------- host launcher ----------------------------------------------
extern "C" void kernel_launch(void* const* d_in, const int* in_sizes, int n_in,
                              void* d_out, int out_size) {
    const int*   input = (const int*)  d_in[0];
    const float* h0    = (const float*)d_in[1];
    const float* c0    = (const float*)d_in[2];
    const float* h1    = (const float*)d_in[3];
    const float* c1    = (const float*)d_in[4];
    const float* h2    = (const float*)d_in[5];
    const float* c2    = (const float*)d_in[6];
    const float* emb_w = (const float*)d_in[7];
    const float* wi0 = (const float*)d_in[8],  *bi0 = (const float*)d_in[9];
    const float* wh0 = (const float*)d_in[10], *bh0 = (const float*)d_in[11];
    const float* wi1 = (const float*)d_in[12], *bi1 = (const float*)d_in[13];
    const float* wh1 = (const float*)d_in[14], *bh1 = (const float*)d_in[15];
    const float* wi2 = (const float*)d_in[16], *bi2 = (const float*)d_in[17];
    const float* wh2 = (const float*)d_in[18], *bh2 = (const float*)d_in[19];
    const float* dec_b = (const float*)d_in[20];
    float* out = (float*)d_out;

    float *x0, *xp0, *hs0, *xp1, *hs1, *xp2, *hs2;
    cudaGetSymbolAddress((void**)&x0,  g_x0);
    cudaGetSymbolAddress((void**)&xp0, g_xpre0);
    cudaGetSymbolAddress((void**)&hs0, g_hs0);
    cudaGetSymbolAddress((void**)&xp1, g_xpre1);
    cudaGetSymbolAddress((void**)&hs1, g_hs1);
    cudaGetSymbolAddress((void**)&xp2, g_xpre2);
    cudaGetSymbolAddress((void**)&hs2, g_hs2);

    const int M = T_ * B_;   // 4480

    // embedding
    embed_k<<<M, 128>>>(input, emb_w);

    // ---- layer 0: 400 -> 1150 ----
    {
        int N = 4 * NHID_, K = NINP_, D = NHID_;
        dim3 grid((N + 127) / 128, M / 128);
        sgemm_nt<<<grid, 256>>>(x0, wi0, bi0, xp0, M, N, K);
        init_hc<<<(B_ * D + 255) / 256, 256>>>(h0, c0, B_ * D);
        int gblocks = (N + 31) / 32;
        int pblocks = (B_ * D + 255) / 256;
        for (int t = 0; t < T_; ++t) {
            lstm_step_gemm<<<gblocks, 256>>>(wh0, bh0, xp0, t, N, D);
            lstm_point<<<pblocks, 256>>>(hs0, t, D);
        }
    }

    // ---- layer 1: 1150 -> 1150 ----
    {
        int N = 4 * NHID_, K = NHID_, D = NHID_;
        dim3 grid((N + 127) / 128, M / 128);
        sgemm_nt<<<grid, 256>>>(hs0, wi1, bi1, xp1, M, N, K);
        init_hc<<<(B_ * D + 255) / 256, 256>>>(h1, c1, B_ * D);
        int gblocks = (N + 31) / 32;
        int pblocks = (B_ * D + 255) / 256;
        for (int t = 0; t < T_; ++t) {
            lstm_step_gemm<<<gblocks, 256>>>(wh1, bh1, xp1, t, N, D);
            lstm_point<<<pblocks, 256>>>(hs1, t, D);
        }
    }

    // ---- layer 2: 1150 -> 400 ----
    {
        int N = 4 * NINP_, K = NHID_, D = NINP_;
        dim3 grid((N + 127) / 128, M / 128);
        sgemm_nt<<<grid, 256>>>(hs1, wi2, bi2, xp2, M, N, K);
        init_hc<<<(B_ * D + 255) / 256, 256>>>(h2, c2, B_ * D);
        int gblocks = (N + 31) / 32;
        int pblocks = (B_ * D + 255) / 256;
        for (int t = 0; t < T_; ++t) {
            lstm_step_gemm<<<gblocks, 256>>>(wh2, bh2, xp2, t, N, D);
            lstm_point<<<pblocks, 256>>>(hs2, t, D);
        }
    }

    // ---- decoder: out[M, NTOK] = hs2 @ emb_w^T + dec_b ----
    {
        dim3 grid((NTOK + 127) / 128, M / 128);
        sgemm_nt<<<grid, 256>>>(hs2, emb_w, dec_b, out, M, NTOK, NINP_);
    }
}

// round 2
// speedup vs baseline: 2.6200x; 2.6200x over previous
#include <cuda_runtime.h>
#include <math.h>
#include <stdint.h>

#define T_ 70
#define B_ 64
#define NTOK 33278
#define NINP_ 400
#define NHID_ 1150
#define DP 1152                 // padded hidden stride (mult of 32)
#define M_ (T_*B_)              // 4480 tokens
#define GS 36                   // smem row stride (words) -> conflict-free frag loads

// ---------------- static scratch --------------------------------------------
__device__ float g_x0   [M_*NINP_];
__device__ float g_xpre0[M_*4*NHID_];
__device__ float g_xpre1[M_*4*NHID_];
__device__ float g_xpre2[M_*4*NINP_];
__device__ float g_hs0  [M_*DP];
__device__ float g_hs1  [M_*DP];
__device__ float g_hs2  [M_*NINP_];
__device__ float g_h    [2][B_*DP];       // double-buffered hidden state
__device__ float g_c    [B_*DP];
__device__ float g_whp  [4*DP*DP];        // packed recurrent weights (reused per layer)
__device__ float g_wip  [4600*DP];        // packed input-proj weights (reused)

// ---------------- helpers ----------------------------------------------------
__device__ __forceinline__ uint32_t f2tf(float x){
    uint32_t r; asm("cvt.rna.tf32.f32 %0, %1;" : "=r"(r) : "f"(x)); return r;
}
__device__ __forceinline__ void mma8(float* c, const uint32_t* a, const uint32_t* b){
    asm volatile("mma.sync.aligned.m16n8k8.row.col.f32.tf32.tf32.f32 "
        "{%0,%1,%2,%3},{%4,%5,%6,%7},{%8,%9},{%0,%1,%2,%3};"
        : "+f"(c[0]),"+f"(c[1]),"+f"(c[2]),"+f"(c[3])
        : "r"(a[0]),"r"(a[1]),"r"(a[2]),"r"(a[3]),"r"(b[0]),"r"(b[1]));
}

// ---------------- embedding gather -------------------------------------------
__global__ void embed_k(const int* __restrict__ inp, const float* __restrict__ emb_w) {
    int token = blockIdx.x;
    int tok   = inp[token];
    const float* src = emb_w + (size_t)tok * NINP_;
    float* dst = g_x0 + (size_t)token * NINP_;
    for (int j = threadIdx.x; j < NINP_; j += blockDim.x) dst[j] = src[j];
}

// ---------------- weight packing ---------------------------------------------
// whp[gate][u][k], zero-padded to DPxDP per gate
__global__ void pack_wh(const float* __restrict__ wh, int D) {
    size_t idx = (size_t)blockIdx.x * 256 + threadIdx.x;
    if (idx >= (size_t)4*DP*DP) return;
    int k = (int)(idx % DP);
    size_t r = idx / DP;
    int u = (int)(r % DP);
    int gate = (int)(r / DP);
    float v = (u < D && k < D) ? wh[((size_t)(gate*D + u))*D + k] : 0.f;
    g_whp[idx] = v;
}
// wip[n][k], k zero-padded to DP
__global__ void pack_wi(const float* __restrict__ wi, int N, int K) {
    size_t idx = (size_t)blockIdx.x * 256 + threadIdx.x;
    if (idx >= (size_t)N*DP) return;
    int k = (int)(idx % DP);
    int n = (int)(idx / DP);
    g_wip[idx] = (k < K) ? wi[(size_t)n*K + k] : 0.f;
}

// ---------------- h/c init ----------------------------------------------------
__global__ void init_hc(const float* __restrict__ h0, const float* __restrict__ c0, int D) {
    int i = blockIdx.x * 256 + threadIdx.x;
    if (i >= B_*DP) return;
    int b = i / DP, u = i - b*DP;
    g_h[0][i] = (u < D) ? h0[b*D + u] : 0.f;
    g_c[i]    = (u < D) ? c0[b*D + u] : 0.f;
}

// ---------------- tf32 NT GEMM:  C[M,N] = A[M,K] * B[N,K]^T + bias[N] --------
// 128x128x32 tile, 256 threads, warp tiles 64x32 (2x4), m16n8k8 HMMA
// Requires M % 128 == 0 (true for all call sites: M=4480)
__global__ __launch_bounds__(256) void gemm_tf32(
    const float* __restrict__ A, int lda,
    const float* __restrict__ B, int ldb,
    const float* __restrict__ bias, float* __restrict__ C,
    int M, int N, int K)
{
    __shared__ uint32_t As[128*GS];
    __shared__ uint32_t Bs[128*GS];
    int tid = threadIdx.x;
    int wid = tid >> 5, lane = tid & 31;
    int g = lane >> 2, tg = lane & 3;
    int wm = wid >> 2, wn = wid & 3;
    int m0 = blockIdx.y * 128, n0 = blockIdx.x * 128;

    float acc[4][4][4];
    #pragma unroll
    for (int i = 0; i < 4; ++i)
        #pragma unroll
        for (int j = 0; j < 4; ++j)
            #pragma unroll
            for (int r = 0; r < 4; ++r) acc[i][j][r] = 0.f;

    for (int k0 = 0; k0 < K; k0 += 32) {
        // A tile: 128 rows x 32 k -> 1024 float4, 4/thread
        #pragma unroll
        for (int it = 0; it < 4; ++it) {
            int f4 = tid + it*256;
            int r = f4 >> 3, q = f4 & 7;
            int gk = k0 + q*4;
            int gm = m0 + r;
            uint4 v;
            if (gk + 3 < K) {
                float4 x = *(const float4*)(A + (size_t)gm*lda + gk);
                v.x=f2tf(x.x); v.y=f2tf(x.y); v.z=f2tf(x.z); v.w=f2tf(x.w);
            } else {
                float xs[4];
                #pragma unroll
                for (int j = 0; j < 4; ++j)
                    xs[j] = (gk + j < K) ? A[(size_t)gm*lda + gk + j] : 0.f;
                v.x=f2tf(xs[0]); v.y=f2tf(xs[1]); v.z=f2tf(xs[2]); v.w=f2tf(xs[3]);
            }
            *(uint4*)(As + r*GS + q*4) = v;
        }
        // B tile
        #pragma unroll
        for (int it = 0; it < 4; ++it) {
            int f4 = tid + it*256;
            int r = f4 >> 3, q = f4 & 7;
            int gk = k0 + q*4;
            int gn = n0 + r;
            uint4 v;
            if (gn < N && gk + 3 < K) {
                float4 x = *(const float4*)(B + (size_t)gn*ldb + gk);
                v.x=f2tf(x.x); v.y=f2tf(x.y); v.z=f2tf(x.z); v.w=f2tf(x.w);
            } else {
                float xs[4];
                #pragma unroll
                for (int j = 0; j < 4; ++j)
                    xs[j] = (gn < N && gk + j < K) ? B[(size_t)gn*ldb + gk + j] : 0.f;
                v.x=f2tf(xs[0]); v.y=f2tf(xs[1]); v.z=f2tf(xs[2]); v.w=f2tf(xs[3]);
            }
            *(uint4*)(Bs + r*GS + q*4) = v;
        }
        __syncthreads();
        #pragma unroll
        for (int ka = 0; ka < 4; ++ka) {
            int kk = ka*8;
            uint32_t a[4][4], b[4][2];
            #pragma unroll
            for (int i = 0; i < 4; ++i) {
                int mr = wm*64 + i*16;
                a[i][0] = As[(mr+g  )*GS + kk + tg];
                a[i][1] = As[(mr+g+8)*GS + kk + tg];
                a[i][2] = As[(mr+g  )*GS + kk + tg + 4];
                a[i][3] = As[(mr+g+8)*GS + kk + tg + 4];
            }
            #pragma unroll
            for (int j = 0; j < 4; ++j) {
                int nc = wn*32 + j*8;
                b[j][0] = Bs[(nc+g)*GS + kk + tg];
                b[j][1] = Bs[(nc+g)*GS + kk + tg + 4];
            }
            #pragma unroll
            for (int i = 0; i < 4; ++i)
                #pragma unroll
                for (int j = 0; j < 4; ++j) mma8(acc[i][j], a[i], b[j]);
        }
        __syncthreads();
    }
    // epilogue
    #pragma unroll
    for (int i = 0; i < 4; ++i) {
        #pragma unroll
        for (int j = 0; j < 4; ++j) {
            int row0 = m0 + wm*64 + i*16 + g;
            int col0 = n0 + wn*32 + j*8 + tg*2;
            if (col0 < N)   C[(size_t)row0*N + col0]       = acc[i][j][0] + bias[col0];
            if (col0+1 < N) C[(size_t)row0*N + col0+1]     = acc[i][j][1] + bias[col0+1];
            if (col0 < N)   C[(size_t)(row0+8)*N + col0]   = acc[i][j][2] + bias[col0];
            if (col0+1 < N) C[(size_t)(row0+8)*N + col0+1] = acc[i][j][3] + bias[col0+1];
        }
    }
}

// ---------------- fused recurrent step ----------------------------------------
// Block b computes gates for hidden units [u0, u0+8) x 4 gates (32 cols) over
// all 64 batch rows via tf32 MMA, then does the full cell update in-kernel.
// grid.x = nchunks*4 so the padded h region is always (re)written to zero.
__global__ __launch_bounds__(256) void lstm_step(
    const float* __restrict__ bh,
    const float* __restrict__ xpre,
    float* __restrict__ hs, int hstride,
    int t, int D, int n4, int parity)
{
    __shared__ uint32_t Hs[64*GS];
    __shared__ uint32_t Ws[32*GS];
    __shared__ float    Gsm[64*33];

    int tid = threadIdx.x, wid = tid >> 5, lane = tid & 31;
    int g = lane >> 2, tg = lane & 3;
    int wm = wid & 3, wn = wid >> 2;     // warp tile: rows 16*wm, cols 16*wn
    int u0 = blockIdx.x * 8;
    const float* hsrc = g_h[parity];
    float*       hdst = g_h[parity ^ 1];

    float acc[2][4];
    #pragma unroll
    for (int j = 0; j < 2; ++j)
        #pragma unroll
        for (int r = 0; r < 4; ++r) acc[j][r] = 0.f;

    int nchunks = (D + 31) >> 5;

    // W row r (0..31): gate = r>>3, unit = u0 + (r&7); whp is zero-padded
    int wr = tid >> 3, wq = tid & 7;
    const float* wrow = g_whp + ((size_t)((wr >> 3)*DP + (u0 + (wr & 7))))*DP + wq*4;

    for (int kc = 0; kc < nchunks; ++kc) {
        int k0 = kc * 32;
        #pragma unroll
        for (int it = 0; it < 2; ++it) {
            int f4 = tid + it*256;
            int r = f4 >> 3, q = f4 & 7;
            float4 x = *(const float4*)(hsrc + r*DP + k0 + q*4);
            uint4 v; v.x=f2tf(x.x); v.y=f2tf(x.y); v.z=f2tf(x.z); v.w=f2tf(x.w);
            *(uint4*)(Hs + r*GS + q*4) = v;
        }
        {
            float4 x = *(const float4*)(wrow + k0);
            uint4 v; v.x=f2tf(x.x); v.y=f2tf(x.y); v.z=f2tf(x.z); v.w=f2tf(x.w);
            *(uint4*)(Ws + wr*GS + wq*4) = v;
        }
        __syncthreads();
        #pragma unroll
        for (int ka = 0; ka < 4; ++ka) {
            int kk = ka*8;
            uint32_t a[4];
            int mr = wm*16;
            a[0] = Hs[(mr+g  )*GS + kk + tg];
            a[1] = Hs[(mr+g+8)*GS + kk + tg];
            a[2] = Hs[(mr+g  )*GS + kk + tg + 4];
            a[3] = Hs[(mr+g+8)*GS + kk + tg + 4];
            #pragma unroll
            for (int j = 0; j < 2; ++j) {
                uint32_t b[2];
                int nc = wn*16 + j*8;
                b[0] = Ws[(nc+g)*GS + kk + tg];
                b[1] = Ws[(nc+g)*GS + kk + tg + 4];
                mma8(acc[j], a, b);
            }
        }
        __syncthreads();
    }

    // stage raw gate pre-activations (recurrent part) into smem
    #pragma unroll
    for (int j = 0; j < 2; ++j) {
        int col = wn*16 + j*8 + tg*2;
        int row = wm*16 + g;
        Gsm[row*33 + col]       = acc[j][0];
        Gsm[row*33 + col + 1]   = acc[j][1];
        Gsm[(row+8)*33 + col]   = acc[j][2];
        Gsm[(row+8)*33 + col+1] = acc[j][3];
    }
    __syncthreads();

    // cell update: 64 batch x 8 units = 512 cells
    const float* xp = xpre + (size_t)t * B_ * n4;
    for (int cell = tid; cell < 512; cell += 256) {
        int b = cell >> 3, uu = cell & 7;
        int u = u0 + uu;
        float hval = 0.f;
        if (u < D) {
            float pf = Gsm[b*33 + uu]      + xp[(size_t)b*n4 + u]       + bh[u];
            float pi = Gsm[b*33 + 8 + uu]  + xp[(size_t)b*n4 + D + u]   + bh[D + u];
            float po = Gsm[b*33 + 16 + uu] + xp[(size_t)b*n4 + 2*D + u] + bh[2*D + u];
            float pg = Gsm[b*33 + 24 + uu] + xp[(size_t)b*n4 + 3*D + u] + bh[3*D + u];
            float f = 1.f / (1.f + expf(-pf));
            float i = 1.f / (1.f + expf(-pi));
            float o = 1.f / (1.f + expf(-po));
            float gv = tanhf(pg);
            float c = f * g_c[b*DP + u] + i * gv;
            g_c[b*DP + u] = c;
            hval = o * tanhf(c);
            hs[(size_t)t * B_ * hstride + (size_t)b * hstride + u] = hval;
        }
        hdst[b*DP + u] = hval;   // keeps pad region zero every step
    }
}

// ---------------- host launcher ------------------------------------------------
extern "C" void kernel_launch(void* const* d_in, const int* in_sizes, int n_in,
                              void* d_out, int out_size) {
    const int*   input = (const int*)  d_in[0];
    const float* h0 = (const float*)d_in[1],  *c0 = (const float*)d_in[2];
    const float* h1 = (const float*)d_in[3],  *c1 = (const float*)d_in[4];
    const float* h2 = (const float*)d_in[5],  *c2 = (const float*)d_in[6];
    const float* emb_w = (const float*)d_in[7];
    const float* wi0 = (const float*)d_in[8],  *bi0 = (const float*)d_in[9];
    const float* wh0 = (const float*)d_in[10], *bh0 = (const float*)d_in[11];
    const float* wi1 = (const float*)d_in[12], *bi1 = (const float*)d_in[13];
    const float* wh1 = (const float*)d_in[14], *bh1 = (const float*)d_in[15];
    const float* wi2 = (const float*)d_in[16], *bi2 = (const float*)d_in[17];
    const float* wh2 = (const float*)d_in[18], *bh2 = (const float*)d_in[19];
    const float* dec_b = (const float*)d_in[20];
    float* out = (float*)d_out;

    float *x0, *xp0, *xp1, *xp2, *hs0, *hs1, *hs2;
    cudaGetSymbolAddress((void**)&x0,  g_x0);
    cudaGetSymbolAddress((void**)&xp0, g_xpre0);
    cudaGetSymbolAddress((void**)&xp1, g_xpre1);
    cudaGetSymbolAddress((void**)&xp2, g_xpre2);
    cudaGetSymbolAddress((void**)&hs0, g_hs0);
    cudaGetSymbolAddress((void**)&hs1, g_hs1);
    cudaGetSymbolAddress((void**)&hs2, g_hs2);
    float *wipp, *dummy;
    cudaGetSymbolAddress((void**)&wipp, g_wip);
    (void)dummy;

    const int MB = M_ / 128;          // 35
    const int HCB = (B_*DP + 255) / 256;

    embed_k<<<M_, 128>>>(input, emb_w);

    // ================= layer 0: 400 -> 1150 =================
    {
        int D = NHID_, N4 = 4*D;
        dim3 gg((N4 + 127)/128, MB);
        gemm_tf32<<<gg, 256>>>(x0, NINP_, wi0, NINP_, bi0, xp0, M_, N4, NINP_);
        pack_wh<<<(4*DP*DP + 255)/256, 256>>>(wh0, D);
        init_hc<<<HCB, 256>>>(h0, c0, D);
        int nch = (D + 31) >> 5;
        for (int t = 0; t < T_; ++t)
            lstm_step<<<nch*4, 256>>>(bh0, xp0, hs0, DP, t, D, N4, t & 1);
    }
    // ================= layer 1: 1150 -> 1150 =================
    {
        int D = NHID_, N4 = 4*D;
        pack_wi<<<(int)(((size_t)N4*DP + 255)/256), 256>>>(wi1, N4, NHID_);
        dim3 gg((N4 + 127)/128, MB);
        gemm_tf32<<<gg, 256>>>(hs0, DP, wipp, DP, bi1, xp1, M_, N4, NHID_);
        pack_wh<<<(4*DP*DP + 255)/256, 256>>>(wh1, D);
        init_hc<<<HCB, 256>>>(h1, c1, D);
        int nch = (D + 31) >> 5;
        for (int t = 0; t < T_; ++t)
            lstm_step<<<nch*4, 256>>>(bh1, xp1, hs1, DP, t, D, N4, t & 1);
    }
    // ================= layer 2: 1150 -> 400 =================
    {
        int D = NINP_, N4 = 4*D;
        pack_wi<<<(int)(((size_t)N4*DP + 255)/256), 256>>>(wi2, N4, NHID_);
        dim3 gg((N4 + 127)/128, MB);
        gemm_tf32<<<gg, 256>>>(hs1, DP, wipp, DP, bi2, xp2, M_, N4, NHID_);
        pack_wh<<<(4*DP*DP + 255)/256, 256>>>(wh2, D);
        init_hc<<<HCB, 256>>>(h2, c2, D);
        int nch = (D + 31) >> 5;
        for (int t = 0; t < T_; ++t)
            lstm_step<<<nch*4, 256>>>(bh2, xp2, hs2, NINP_, t, D, N4, t & 1);
    }
    // ================= decoder: out = hs2 @ emb_w^T + dec_b =================
    {
        dim3 gg((NTOK + 127)/128, MB);
        gemm_tf32<<<gg, 256>>>(hs2, NINP_, emb_w, NINP_, dec_b, out, M_, NTOK, NINP_);
    }
}

// round 3
// speedup vs baseline: 4.8792x; 1.8623x over previous
#include <cuda_runtime.h>
#include <math.h>
#include <stdint.h>

#define T_ 70
#define B_ 64
#define NTOK 33278
#define NINP_ 400
#define NHID_ 1150
#define DP 1152                 // padded hidden stride
#define KP0 416                 // padded 400-dim
#define M_ (T_*B_)              // 4480
#define GS 36                   // smem row stride (words)
#define STAGES 3

// ---------------- static scratch ------------------------------------------
__device__ float g_x0   [M_*KP0];
__device__ float g_xpre0[M_*4*NHID_];
__device__ float g_xpre1[M_*4*NHID_];
__device__ float g_xpre2[M_*4*NINP_];
__device__ float g_hs0  [M_*DP];
__device__ float g_hs1  [M_*DP];
__device__ float g_hs2  [M_*KP0];
__device__ float g_h    [2][B_*DP];
__device__ float g_whp  [4*DP*DP];        // packed recurrent weights (per layer reuse)
__device__ float g_wip  [4608*DP];        // packed input-proj weights (reuse)
__device__ float g_dec  [33408*KP0];      // packed decoder weights (emb_w)
__device__ unsigned int g_ctr;            // persistent-kernel barrier counter

// ---------------- helpers -------------------------------------------------
__device__ __forceinline__ uint32_t f2tf(float x){
    uint32_t r; asm("cvt.rna.tf32.f32 %0, %1;" : "=r"(r) : "f"(x)); return r;
}
__device__ __forceinline__ float f2tff(float x){
    uint32_t r = f2tf(x); return __uint_as_float(r);
}
__device__ __forceinline__ void mma8(float* c, const uint32_t* a, const uint32_t* b){
    asm volatile("mma.sync.aligned.m16n8k8.row.col.f32.tf32.tf32.f32 "
        "{%0,%1,%2,%3},{%4,%5,%6,%7},{%8,%9},{%0,%1,%2,%3};"
        : "+f"(c[0]),"+f"(c[1]),"+f"(c[2]),"+f"(c[3])
        : "r"(a[0]),"r"(a[1]),"r"(a[2]),"r"(a[3]),"r"(b[0]),"r"(b[1]));
}
__device__ __forceinline__ void cpa16(void* smem, const void* gmem){
    uint32_t s = (uint32_t)__cvta_generic_to_shared(smem);
    asm volatile("cp.async.cg.shared.global [%0], [%1], 16;" :: "r"(s), "l"(gmem));
}
__device__ __forceinline__ void cpcommit(){ asm volatile("cp.async.commit_group;"); }
template<int N> __device__ __forceinline__ void cpwait(){ asm volatile("cp.async.wait_group %0;" :: "n"(N)); }

// ---------------- embedding gather (tf32-rounded, padded stride) ----------
__global__ void embed_k(const int* __restrict__ inp, const float* __restrict__ emb_w) {
    int token = blockIdx.x;
    int tok   = inp[token];
    const float* src = emb_w + (size_t)tok * NINP_;
    float* dst = g_x0 + (size_t)token * KP0;
    for (int j = threadIdx.x; j < KP0; j += blockDim.x)
        dst[j] = (j < NINP_) ? f2tff(src[j]) : 0.f;
}

// ---------------- pack B[N,K] -> dst[Npad, KP] tf32-rounded, zero pad -----
__global__ void pack_b(const float* __restrict__ src, float* __restrict__ dst,
                       int N, int K, int KP, long total) {
    long idx = (long)blockIdx.x * 256 + threadIdx.x;
    if (idx >= total) return;
    int k = (int)(idx % KP);
    long n = idx / KP;
    dst[idx] = (n < N && k < K) ? f2tff(src[n*K + k]) : 0.f;
}

// ---------------- pack recurrent weights: rows gate*1152+u, stride Kp -----
__global__ void pack_wh(const float* __restrict__ wh, int D, int Kp, long total) {
    long idx = (long)blockIdx.x * 256 + threadIdx.x;
    if (idx >= total) return;
    int k = (int)(idx % Kp);
    long r = idx / Kp;
    int u = (int)(r % DP);
    int gate = (int)(r / DP);
    g_whp[idx] = (u < D && k < D) ? f2tff(wh[((size_t)(gate*D + u))*D + k]) : 0.f;
}

// ---------------- h init + barrier reset ----------------------------------
__global__ void init_hc(const float* __restrict__ h0, int D) {
    int i = blockIdx.x * 256 + threadIdx.x;
    if (i == 0) g_ctr = 0;
    if (i >= B_*DP) return;
    int b = i / DP, u = i - b*DP;
    g_h[0][i] = (u < D) ? f2tff(h0[b*D + u]) : 0.f;
}

// ---------------- pipelined tf32 GEMM: C = A[M,K] * B[N,K]^T + bias -------
// A,B already tf32 bit patterns; K%32==0; M%128==0; B rows padded to grid*128
__global__ __launch_bounds__(256) void gemm_tc(
    const float* __restrict__ A, int lda,
    const float* __restrict__ B, int ldb,
    const float* __restrict__ bias, float* __restrict__ C,
    int N, int K)
{
    extern __shared__ uint32_t sm[];
    uint32_t* As = sm;                      // STAGES * 128*GS
    uint32_t* Bs = sm + STAGES*128*GS;
    int tid = threadIdx.x;
    int wid = tid >> 5, lane = tid & 31;
    int g = lane >> 2, tg = lane & 3;
    int wm = wid >> 2, wn = wid & 3;
    int m0 = blockIdx.y * 128, n0 = blockIdx.x * 128;
    int KT = K >> 5;

    int lr = tid >> 3, lq = tid & 7;        // ld row base / quad

    float acc[4][4][4];
    #pragma unroll
    for (int i = 0; i < 4; ++i)
        #pragma unroll
        for (int j = 0; j < 4; ++j)
            #pragma unroll
            for (int r = 0; r < 4; ++r) acc[i][j][r] = 0.f;

    // prologue: issue stages 0..STAGES-2
    #pragma unroll
    for (int s = 0; s < STAGES-1; ++s) {
        if (s < KT) {
            int k0 = s*32;
            #pragma unroll
            for (int it = 0; it < 4; ++it) {
                int r = lr + it*32;
                cpa16(&As[(s*128 + r)*GS + lq*4], A + (size_t)(m0+r)*lda + k0 + lq*4);
                cpa16(&Bs[(s*128 + r)*GS + lq*4], B + (size_t)(n0+r)*ldb + k0 + lq*4);
            }
        }
        cpcommit();
    }

    for (int kt = 0; kt < KT; ++kt) {
        cpwait<STAGES-2>();
        __syncthreads();
        {   // issue stage kt+STAGES-1
            int kl = kt + STAGES - 1;
            if (kl < KT) {
                int s = kl % STAGES, k0 = kl*32;
                #pragma unroll
                for (int it = 0; it < 4; ++it) {
                    int r = lr + it*32;
                    cpa16(&As[(s*128 + r)*GS + lq*4], A + (size_t)(m0+r)*lda + k0 + lq*4);
                    cpa16(&Bs[(s*128 + r)*GS + lq*4], B + (size_t)(n0+r)*ldb + k0 + lq*4);
                }
            }
            cpcommit();
        }
        const uint32_t* Ast = As + (kt % STAGES)*128*GS;
        const uint32_t* Bst = Bs + (kt % STAGES)*128*GS;
        #pragma unroll
        for (int ka = 0; ka < 4; ++ka) {
            int kk = ka*8;
            uint32_t a[4][4], b[4][2];
            #pragma unroll
            for (int i = 0; i < 4; ++i) {
                int mr = wm*64 + i*16;
                a[i][0] = Ast[(mr+g  )*GS + kk + tg];
                a[i][1] = Ast[(mr+g+8)*GS + kk + tg];
                a[i][2] = Ast[(mr+g  )*GS + kk + tg + 4];
                a[i][3] = Ast[(mr+g+8)*GS + kk + tg + 4];
            }
            #pragma unroll
            for (int j = 0; j < 4; ++j) {
                int nc = wn*32 + j*8;
                b[j][0] = Bst[(nc+g)*GS + kk + tg];
                b[j][1] = Bst[(nc+g)*GS + kk + tg + 4];
            }
            #pragma unroll
            for (int i = 0; i < 4; ++i)
                #pragma unroll
                for (int j = 0; j < 4; ++j) mma8(acc[i][j], a[i], b[j]);
        }
        __syncthreads();
    }

    // epilogue (N even at all call sites)
    #pragma unroll
    for (int i = 0; i < 4; ++i) {
        #pragma unroll
        for (int j = 0; j < 4; ++j) {
            int row0 = m0 + wm*64 + i*16 + g;
            int col0 = n0 + wn*32 + j*8 + tg*2;
            if (col0 < N) {
                float b0 = bias[col0], b1 = bias[col0+1];
                float2 v0 = make_float2(acc[i][j][0] + b0, acc[i][j][1] + b1);
                float2 v1 = make_float2(acc[i][j][2] + b0, acc[i][j][3] + b1);
                *(float2*)(C + (size_t)row0*N + col0)     = v0;
                *(float2*)(C + (size_t)(row0+8)*N + col0) = v1;
            }
        }
    }
}

// ---------------- persistent recurrent layer -------------------------------
// One launch runs all T_ timesteps. Block = 8 hidden units x 4 gates (32 cols)
// over 64 batch rows. Weights resident in smem; c resident in smem; grid-wide
// spin barrier between steps. Requires gridDim.x <= #SMs (all blocks resident).
__global__ __launch_bounds__(256) void lstm_persist(
    const float* __restrict__ bh, const float* __restrict__ c0in,
    const float* __restrict__ xpre, float* __restrict__ hs,
    int hstride, int D, int n4, int KT, int Kp)
{
    extern __shared__ uint32_t Wsm[];          // 32 * (Kp+4)
    __shared__ uint32_t Hsm[3][64*GS];
    __shared__ float Gsm[64*33];
    __shared__ float c_sm[512];

    int KS = Kp + 4;
    int tid = threadIdx.x, wid = tid >> 5, lane = tid & 31;
    int g = lane >> 2, tg = lane & 3;
    int wm = wid & 3, wn = wid >> 2;
    int u0 = blockIdx.x * 8;

    // ---- load weight slice into smem (once) ----
    int nq = Kp >> 2;                          // float4 per row
    for (int idx = tid; idx < 32*nq; idx += 256) {
        int r = idx / nq, q = idx - r*nq;
        int gate = r >> 3, uu = r & 7;
        const float4 v = *(const float4*)(g_whp + ((size_t)(gate*DP + u0 + uu))*Kp + q*4);
        *(float4*)((float*)Wsm + r*KS + q*4) = v;
    }
    // ---- c init ----
    for (int cell = tid; cell < 512; cell += 256) {
        int b = cell >> 3, uu = cell & 7;
        int u = u0 + uu;
        c_sm[cell] = (u < D) ? c0in[b*D + u] : 0.f;
    }
    // ---- bh slice ----
    float bhv[4];
    {
        int uu = tid & 7, u = u0 + uu;
        #pragma unroll
        for (int gt = 0; gt < 4; ++gt)
            bhv[gt] = (u < D) ? bh[gt*D + u] : 0.f;
    }
    __syncthreads();

    int lr = tid >> 3, lq = tid & 7;           // h-tile ld coords

    for (int t = 0; t < T_; ++t) {
        const float* hsrc = g_h[t & 1];
        float*       hdst = g_h[(t & 1) ^ 1];
        const float* xp = xpre + (size_t)t * B_ * n4;

        // xpre prefetch into registers (2 cells/thread x 4 gates)
        float xg[2][4];
        #pragma unroll
        for (int cc = 0; cc < 2; ++cc) {
            int cell = tid + cc*256;
            int b = cell >> 3, uu = cell & 7;
            int u = u0 + uu;
            #pragma unroll
            for (int gt = 0; gt < 4; ++gt)
                xg[cc][gt] = (u < D) ? xp[(size_t)b*n4 + gt*D + u] : 0.f;
        }

        // prologue: h chunks 0,1
        #pragma unroll
        for (int s = 0; s < 2; ++s) {
            if (s < KT) {
                int k0 = s*32;
                #pragma unroll
                for (int it = 0; it < 2; ++it) {
                    int r = lr + it*32;
                    cpa16(&Hsm[s][r*GS + lq*4], hsrc + (size_t)r*DP + k0 + lq*4);
                }
            }
            cpcommit();
        }

        float acc[2][4];
        #pragma unroll
        for (int j = 0; j < 2; ++j)
            #pragma unroll
            for (int r = 0; r < 4; ++r) acc[j][r] = 0.f;

        for (int kc = 0; kc < KT; ++kc) {
            cpwait<1>();
            __syncthreads();
            {
                int kl = kc + 2;
                if (kl < KT) {
                    int s = kl % 3, k0 = kl*32;
                    #pragma unroll
                    for (int it = 0; it < 2; ++it) {
                        int r = lr + it*32;
                        cpa16(&Hsm[s][r*GS + lq*4], hsrc + (size_t)r*DP + k0 + lq*4);
                    }
                }
                cpcommit();
            }
            const uint32_t* Hst = Hsm[kc % 3];
            int k0 = kc*32;
            #pragma unroll
            for (int ka = 0; ka < 4; ++ka) {
                int kk = ka*8;
                uint32_t a[4];
                int mr = wm*16;
                a[0] = Hst[(mr+g  )*GS + kk + tg];
                a[1] = Hst[(mr+g+8)*GS + kk + tg];
                a[2] = Hst[(mr+g  )*GS + kk + tg + 4];
                a[3] = Hst[(mr+g+8)*GS + kk + tg + 4];
                #pragma unroll
                for (int j = 0; j < 2; ++j) {
                    uint32_t b[2];
                    int nc = wn*16 + j*8;
                    b[0] = Wsm[(nc+g)*KS + k0 + kk + tg];
                    b[1] = Wsm[(nc+g)*KS + k0 + kk + tg + 4];
                    mma8(acc[j], a, b);
                }
            }
            __syncthreads();
        }

        // exchange gate pre-activations through smem
        #pragma unroll
        for (int j = 0; j < 2; ++j) {
            int col = wn*16 + j*8 + tg*2;
            int row = wm*16 + g;
            Gsm[row*33 + col]       = acc[j][0];
            Gsm[row*33 + col + 1]   = acc[j][1];
            Gsm[(row+8)*33 + col]   = acc[j][2];
            Gsm[(row+8)*33 + col+1] = acc[j][3];
        }
        __syncthreads();

        // cell update
        #pragma unroll
        for (int cc = 0; cc < 2; ++cc) {
            int cell = tid + cc*256;
            int b = cell >> 3, uu = cell & 7;
            int u = u0 + uu;
            float hval = 0.f;
            if (u < D) {
                float pf = Gsm[b*33 + uu]      + xg[cc][0] + bhv[0];
                float pi = Gsm[b*33 + 8 + uu]  + xg[cc][1] + bhv[1];
                float po = Gsm[b*33 + 16 + uu] + xg[cc][2] + bhv[2];
                float pg = Gsm[b*33 + 24 + uu] + xg[cc][3] + bhv[3];
                float f = 1.f / (1.f + expf(-pf));
                float i = 1.f / (1.f + expf(-pi));
                float o = 1.f / (1.f + expf(-po));
                float gv = tanhf(pg);
                float c = f * c_sm[cell] + i * gv;
                c_sm[cell] = c;
                hval = f2tff(o * tanhf(c));
                hs[((size_t)t * B_ + b) * hstride + u] = hval;
            }
            hdst[b*DP + u] = hval;
        }

        // grid-wide barrier
        __threadfence();
        __syncthreads();
        if (tid == 0) {
            atomicAdd(&g_ctr, 1u);
            unsigned tgt = (unsigned)(t + 1) * gridDim.x;
            while (atomicAdd(&g_ctr, 0u) < tgt) {}
            __threadfence();
        }
        __syncthreads();
    }
}

// ---------------- host launcher --------------------------------------------
extern "C" void kernel_launch(void* const* d_in, const int* in_sizes, int n_in,
                              void* d_out, int out_size) {
    const int*   input = (const int*)  d_in[0];
    const float* h0 = (const float*)d_in[1],  *c0 = (const float*)d_in[2];
    const float* h1 = (const float*)d_in[3],  *c1 = (const float*)d_in[4];
    const float* h2 = (const float*)d_in[5],  *c2 = (const float*)d_in[6];
    const float* emb_w = (const float*)d_in[7];
    const float* wi0 = (const float*)d_in[8],  *bi0 = (const float*)d_in[9];
    const float* wh0 = (const float*)d_in[10], *bh0 = (const float*)d_in[11];
    const float* wi1 = (const float*)d_in[12], *bi1 = (const float*)d_in[13];
    const float* wh1 = (const float*)d_in[14], *bh1 = (const float*)d_in[15];
    const float* wi2 = (const float*)d_in[16], *bi2 = (const float*)d_in[17];
    const float* wh2 = (const float*)d_in[18], *bh2 = (const float*)d_in[19];
    const float* dec_b = (const float*)d_in[20];
    float* out = (float*)d_out;

    float *x0, *xp0, *xp1, *xp2, *hs0, *hs1, *hs2, *wip, *dec;
    cudaGetSymbolAddress((void**)&x0,  g_x0);
    cudaGetSymbolAddress((void**)&xp0, g_xpre0);
    cudaGetSymbolAddress((void**)&xp1, g_xpre1);
    cudaGetSymbolAddress((void**)&xp2, g_xpre2);
    cudaGetSymbolAddress((void**)&hs0, g_hs0);
    cudaGetSymbolAddress((void**)&hs1, g_hs1);
    cudaGetSymbolAddress((void**)&hs2, g_hs2);
    cudaGetSymbolAddress((void**)&wip, g_wip);
    cudaGetSymbolAddress((void**)&dec, g_dec);

    static int attr_done = 0;
    if (!attr_done) {
        cudaFuncSetAttribute(gemm_tc, cudaFuncAttributeMaxDynamicSharedMemorySize,
                             STAGES*128*GS*4*2);
        cudaFuncSetAttribute(lstm_persist, cudaFuncAttributeMaxDynamicSharedMemorySize,
                             32*(DP+4)*4);
        attr_done = 1;
    }

    const int MB = M_ / 128;                  // 35
    const int HCB = (B_*DP + 255) / 256;
    const int gemm_smem = STAGES*128*GS*4*2;  // 110.6 KB

    embed_k<<<M_, 128>>>(input, emb_w);

    // ================= layer 0: 400 -> 1150 =================
    {
        int D = NHID_, N4 = 4*D, Kp = KP0;
        long tb = (long)4608*Kp;
        pack_b<<<(int)((tb+255)/256), 256>>>(wi0, wip, N4, NINP_, Kp, tb);
        dim3 gg(36, MB);
        gemm_tc<<<gg, 256, gemm_smem>>>(x0, Kp, wip, Kp, bi0, xp0, N4, Kp);
        long tw = (long)4*DP*DP;
        pack_wh<<<(int)((tw+255)/256), 256>>>(wh0, D, DP, tw);
        init_hc<<<HCB, 256>>>(h0, D);
        lstm_persist<<<144, 256, 32*(DP+4)*4>>>(bh0, c0, xp0, hs0, DP, D, N4, 36, DP);
    }
    // ================= layer 1: 1150 -> 1150 =================
    {
        int D = NHID_, N4 = 4*D, Kp = DP;
        long tb = (long)4608*Kp;
        pack_b<<<(int)((tb+255)/256), 256>>>(wi1, wip, N4, NHID_, Kp, tb);
        dim3 gg(36, MB);
        gemm_tc<<<gg, 256, gemm_smem>>>(hs0, DP, wip, Kp, bi1, xp1, N4, Kp);
        long tw = (long)4*DP*DP;
        pack_wh<<<(int)((tw+255)/256), 256>>>(wh1, D, DP, tw);
        init_hc<<<HCB, 256>>>(h1, D);
        lstm_persist<<<144, 256, 32*(DP+4)*4>>>(bh1, c1, xp1, hs1, DP, D, N4, 36, DP);
    }
    // ================= layer 2: 1150 -> 400 =================
    {
        int D = NINP_, N4 = 4*D, Kp = DP;
        long tb = (long)1664*Kp;
        pack_b<<<(int)((tb+255)/256), 256>>>(wi2, wip, N4, NHID_, Kp, tb);
        dim3 gg(13, MB);
        gemm_tc<<<gg, 256, gemm_smem>>>(hs1, DP, wip, Kp, bi2, xp2, N4, Kp);
        long tw = (long)4*DP*KP0;
        pack_wh<<<(int)((tw+255)/256), 256>>>(wh2, D, KP0, tw);
        init_hc<<<HCB, 256>>>(h2, D);
        lstm_persist<<<52, 256, 32*(KP0+4)*4>>>(bh2, c2, xp2, hs2, KP0, D, N4, 13, KP0);
    }
    // ================= decoder =================
    {
        long tb = (long)33408*KP0;
        pack_b<<<(int)((tb+255)/256), 256>>>(emb_w, dec, NTOK, NINP_, KP0, tb);
        dim3 gg(261, MB);
        gemm_tc<<<gg, 256, gemm_smem>>>(hs2, KP0, dec, KP0, dec_b, out, NTOK, KP0);
    }
}